// round 10
// baseline (speedup 1.0000x reference)
#include <cuda_runtime.h>
#include <cstdint>
#include <stdint.h>
#include <math.h>

#define B_ 8
#define N_ 1024
#define C_ 768
#define H_ 12
#define DH_ 64
#define NIMG_ 784

// Scratch (static device arrays: allocation-free per harness rules)
__device__ float g_qkv[B_ * N_ * 3 * C_];       // [8192][2304]
__device__ float g_q[B_ * H_ * N_ * DH_];       // [bh][n][d]
__device__ float g_k[B_ * H_ * N_ * DH_];
__device__ float g_v[B_ * H_ * N_ * DH_];
__device__ float g_ao[B_ * N_ * C_];            // attention out, [b*N+n][C]

__device__ __forceinline__ unsigned f2tf32(float f) {
    unsigned u;
    asm("cvt.rna.tf32.f32 %0, %1;" : "=r"(u) : "f"(f));
    return u;
}

__device__ __forceinline__ void mma_tf32(float* d, const unsigned* a, const unsigned* b) {
    asm volatile(
        "mma.sync.aligned.m16n8k8.row.col.f32.tf32.tf32.f32 "
        "{%0,%1,%2,%3}, {%4,%5,%6,%7}, {%8,%9}, {%0,%1,%2,%3};"
        : "+f"(d[0]), "+f"(d[1]), "+f"(d[2]), "+f"(d[3])
        : "r"(a[0]), "r"(a[1]), "r"(a[2]), "r"(a[3]), "r"(b[0]), "r"(b[1]));
}

__device__ __forceinline__ unsigned sptr(const void* p) {
    return (unsigned)__cvta_generic_to_shared(p);
}

__device__ __forceinline__ void ldsm_x4(unsigned& r0, unsigned& r1,
                                        unsigned& r2, unsigned& r3, unsigned addr) {
    asm volatile("ldmatrix.sync.aligned.m8n8.x4.shared.b16 {%0,%1,%2,%3}, [%4];"
        : "=r"(r0), "=r"(r1), "=r"(r2), "=r"(r3) : "r"(addr));
}

// ---------------------------------------------------------------------------
// TF32 legacy-MMA GEMM, fat warp tiles: block 128(M)x256(N), BK=16,
// 256 threads = 8 warps in 2(m)x4(n), warp tile 64x64.
// Per ks-step/warp: 8 LDSM.x4 feed 32 MMAs (0.25 LDSM/MMA).
// Double-buffered smem, 1 barrier per iteration.
// ---------------------------------------------------------------------------
#define BKg 16
#define SSTR 20  // smem row stride (words): rows 16B-aligned, LDSM conflict-free
#define SA_WORDS (128 * SSTR)
#define SB_WORDS (256 * SSTR)
#define GEMM_SMEM_BYTES ((2 * SA_WORDS + 2 * SB_WORDS) * 4)

__global__ void __launch_bounds__(256, 1) mma_gemm_bias(
    const float* __restrict__ A, const float* __restrict__ W,
    const float* __restrict__ bias, float* __restrict__ out,
    int M, int Nout, int K)
{
    extern __shared__ __align__(16) unsigned smg[];
    unsigned* sA[2] = { smg, smg + SA_WORDS };
    unsigned* sB[2] = { smg + 2 * SA_WORDS, smg + 2 * SA_WORDS + SB_WORDS };

    const int t = threadIdx.x;
    const int lane = t & 31;
    const int warp = t >> 5;
    const int wm = (warp & 1) * 64;       // warp m offset
    const int wn = (warp >> 1) * 64;      // warp n offset
    const int m0 = blockIdx.y * 128;
    const int n0 = blockIdx.x * 256;

    // A tile 128x16: 512 float4, 2/thread. B tile 256x16: 1024 float4, 4/thread.
    const int ra0 = (t + 0) >> 2, ca0 = ((t + 0) & 3) * 4;
    const int ra1 = (t + 256) >> 2, ca1 = ((t + 256) & 3) * 4;
    int rb[4], cb[4];
#pragma unroll
    for (int i = 0; i < 4; i++) { rb[i] = (t + i * 256) >> 2; cb[i] = ((t + i * 256) & 3) * 4; }

    // LDSM per-lane offsets (words)
    const int lg = lane >> 3, lr = lane & 7;
    const int a_off = ((lg & 1) * 8 + lr) * SSTR + (lg >> 1) * 4;
    const int b_off = ((lg >> 1) * 8 + lr) * SSTR + (lg & 1) * 4;

    float acc[4][8][4];
#pragma unroll
    for (int i = 0; i < 4; i++)
#pragma unroll
        for (int j = 0; j < 8; j++)
#pragma unroll
            for (int v = 0; v < 4; v++) acc[i][j][v] = 0.f;

    const int fr = lane >> 2;
    const int fc = lane & 3;

    float4 pa0, pa1, pb[4];
    pa0 = *(const float4*)(A + (size_t)(m0 + ra0) * K + ca0);
    pa1 = *(const float4*)(A + (size_t)(m0 + ra1) * K + ca1);
#pragma unroll
    for (int i = 0; i < 4; i++)
        pb[i] = *(const float4*)(W + (size_t)(n0 + rb[i]) * K + cb[i]);
    {
        *(uint4*)&sA[0][ra0 * SSTR + ca0] =
            make_uint4(f2tf32(pa0.x), f2tf32(pa0.y), f2tf32(pa0.z), f2tf32(pa0.w));
        *(uint4*)&sA[0][ra1 * SSTR + ca1] =
            make_uint4(f2tf32(pa1.x), f2tf32(pa1.y), f2tf32(pa1.z), f2tf32(pa1.w));
#pragma unroll
        for (int i = 0; i < 4; i++)
            *(uint4*)&sB[0][rb[i] * SSTR + cb[i]] =
                make_uint4(f2tf32(pb[i].x), f2tf32(pb[i].y), f2tf32(pb[i].z), f2tf32(pb[i].w));
    }
    __syncthreads();

    const int nIter = K / BKg;
    for (int it = 0; it < nIter; it++) {
        const int buf = it & 1;
        const bool has_next = (it + 1) < nIter;

        if (has_next) {
            int kn = (it + 1) * BKg;
            pa0 = *(const float4*)(A + (size_t)(m0 + ra0) * K + kn + ca0);
            pa1 = *(const float4*)(A + (size_t)(m0 + ra1) * K + kn + ca1);
#pragma unroll
            for (int i = 0; i < 4; i++)
                pb[i] = *(const float4*)(W + (size_t)(n0 + rb[i]) * K + kn + cb[i]);
        }

        const unsigned* cA = sA[buf];
        const unsigned* cB = sB[buf];
#pragma unroll
        for (int ks = 0; ks < 2; ks++) {
            unsigned areg[4][4], breg[8][2];
#pragma unroll
            for (int mf = 0; mf < 4; mf++)
                ldsm_x4(areg[mf][0], areg[mf][1], areg[mf][2], areg[mf][3],
                        sptr(cA + (wm + mf * 16) * SSTR + ks * 8 + a_off));
#pragma unroll
            for (int np = 0; np < 4; np++)
                ldsm_x4(breg[np * 2][0], breg[np * 2][1],
                        breg[np * 2 + 1][0], breg[np * 2 + 1][1],
                        sptr(cB + (wn + np * 16) * SSTR + ks * 8 + b_off));
#pragma unroll
            for (int mf = 0; mf < 4; mf++)
#pragma unroll
                for (int nf = 0; nf < 8; nf++)
                    mma_tf32(acc[mf][nf], areg[mf], breg[nf]);
        }

        if (has_next) {
            unsigned* nA = sA[buf ^ 1];
            unsigned* nB = sB[buf ^ 1];
            *(uint4*)&nA[ra0 * SSTR + ca0] =
                make_uint4(f2tf32(pa0.x), f2tf32(pa0.y), f2tf32(pa0.z), f2tf32(pa0.w));
            *(uint4*)&nA[ra1 * SSTR + ca1] =
                make_uint4(f2tf32(pa1.x), f2tf32(pa1.y), f2tf32(pa1.z), f2tf32(pa1.w));
#pragma unroll
            for (int i = 0; i < 4; i++)
                *(uint4*)&nB[rb[i] * SSTR + cb[i]] =
                    make_uint4(f2tf32(pb[i].x), f2tf32(pb[i].y), f2tf32(pb[i].z), f2tf32(pb[i].w));
            __syncthreads();
        }
    }

    // epilogue
#pragma unroll
    for (int mf = 0; mf < 4; mf++) {
        int row = m0 + wm + mf * 16 + fr;
#pragma unroll
        for (int nf = 0; nf < 8; nf++) {
            int col = n0 + wn + nf * 8 + 2 * fc;
            float bx = bias[col], by = bias[col + 1];
            float2 lo = make_float2(acc[mf][nf][0] + bx, acc[mf][nf][1] + by);
            float2 hi = make_float2(acc[mf][nf][2] + bx, acc[mf][nf][3] + by);
            *(float2*)(out + (size_t)row * Nout + col) = lo;
            *(float2*)(out + (size_t)(row + 8) * Nout + col) = hi;
        }
    }
}

// ---------------------------------------------------------------------------
// RoPE2D + split qkv into q,k,v with [b*H+h][n][d] layout.
// ---------------------------------------------------------------------------
__global__ void rope_split_kernel(const int* __restrict__ pos2d)
{
    int idx = blockIdx.x * blockDim.x + threadIdx.x;
    const int total = B_ * N_ * H_ * DH_;
    if (idx >= total) return;

    int d = idx & 63;
    int h = (idx >> 6) % H_;
    int n = (idx / (H_ * DH_)) % N_;
    int b = idx / (N_ * H_ * DH_);

    const float* row = g_qkv + (size_t)(b * N_ + n) * (3 * C_);
    float qv = row[h * 64 + d];
    float kv = row[C_ + h * 64 + d];
    float vv = row[2 * C_ + h * 64 + d];

    if (n < NIMG_) {
        int half = d >> 5;
        int dl = d & 31;
        int f = dl & 15;
        int pos = pos2d[((size_t)b * NIMG_ + n) * 2 + half];
        float inv = exp2f(-0.41524101186f * (float)f);  // 100^(-f/16)
        float ang = (float)pos * inv;
        float s, c;
        sincosf(ang, &s, &c);
        int pd = (dl < 16) ? (d + 16) : (d - 16);
        float sign = (dl < 16) ? -1.0f : 1.0f;
        float qp = row[h * 64 + pd];
        float kp = row[C_ + h * 64 + pd];
        qv = qv * c + sign * qp * s;
        kv = kv * c + sign * kp * s;
    }

    size_t o = ((size_t)(b * H_ + h) * N_ + n) * DH_ + d;
    g_q[o] = qv; g_k[o] = kv; g_v[o] = vv;
}

// ---------------------------------------------------------------------------
// TF32 tensor-core flash attention + LDSM fragment loads (R7 measured-good).
// Grid: (N/64, B*H). 128 threads = 4 warps, warp w owns q-rows [16w,16w+16).
// ---------------------------------------------------------------------------
#define ASTR 68
#define ATTN_SMEM_BYTES (4 * 64 * ASTR * 4)

__global__ void __launch_bounds__(128) attn_mma_kernel(float* __restrict__ out)
{
    extern __shared__ __align__(16) unsigned smu[];
    unsigned* sQ = smu;
    unsigned* sK = smu + 64 * ASTR;
    unsigned* sVt = smu + 2 * 64 * ASTR;
    unsigned* sP = smu + 3 * 64 * ASTR;

    const int t = threadIdx.x;
    const int lane = t & 31;
    const int w = t >> 5;
    const int fr = lane >> 2;
    const int fc = lane & 3;
    const int wm = w * 16;
    const int bh = blockIdx.y;
    const int q0 = blockIdx.x * 64;

    const int lg = lane >> 3, lr = lane & 7;
    const int a_off = ((lg & 1) * 8 + lr) * ASTR + (lg >> 1) * 4;
    const int b_off = ((lg >> 1) * 8 + lr) * ASTR + (lg & 1) * 4;

    const float* Qg = g_q + ((size_t)bh * N_ + q0) * DH_;
    const float* Kg = g_k + (size_t)bh * N_ * DH_;
    const float* Vg = g_v + (size_t)bh * N_ * DH_;

#pragma unroll
    for (int i = 0; i < 8; i++) {
        int idx4 = t + i * 128;
        int r = idx4 >> 4;
        int c4 = (idx4 & 15) * 4;
        float4 v4 = *(const float4*)(Qg + (size_t)r * 64 + c4);
        uint4 u = make_uint4(f2tf32(v4.x), f2tf32(v4.y), f2tf32(v4.z), f2tf32(v4.w));
        *(uint4*)&sQ[r * ASTR + c4] = u;
    }

    float m0 = -1e30f, m1 = -1e30f, l0 = 0.f, l1 = 0.f;
    float oacc[8][4];
#pragma unroll
    for (int nf = 0; nf < 8; nf++)
#pragma unroll
        for (int v = 0; v < 4; v++) oacc[nf][v] = 0.f;

    const int vd = 32 * (w & 1) + lane;
    const int vkb = (w >> 1) * 4;

    for (int kb = 0; kb < N_; kb += 64) {
        if (kb) __syncthreads();
#pragma unroll
        for (int i = 0; i < 8; i++) {
            int idx4 = t + i * 128;
            int r = idx4 >> 4;
            int c4 = (idx4 & 15) * 4;
            float4 k4 = *(const float4*)(Kg + (size_t)(kb + r) * 64 + c4);
            uint4 u = make_uint4(f2tf32(k4.x), f2tf32(k4.y), f2tf32(k4.z), f2tf32(k4.w));
            *(uint4*)&sK[r * ASTR + c4] = u;
        }
#pragma unroll
        for (int i = 0; i < 8; i++) {
            int key0 = vkb + i * 8;
            float v0 = Vg[(size_t)(kb + key0 + 0) * 64 + vd];
            float v1 = Vg[(size_t)(kb + key0 + 1) * 64 + vd];
            float v2 = Vg[(size_t)(kb + key0 + 2) * 64 + vd];
            float v3 = Vg[(size_t)(kb + key0 + 3) * 64 + vd];
            uint4 u = make_uint4(f2tf32(v0), f2tf32(v1), f2tf32(v2), f2tf32(v3));
            *(uint4*)&sVt[vd * ASTR + key0] = u;
        }
        __syncthreads();

        float sacc[8][4];
#pragma unroll
        for (int nf = 0; nf < 8; nf++)
#pragma unroll
            for (int v = 0; v < 4; v++) sacc[nf][v] = 0.f;
#pragma unroll
        for (int kc = 0; kc < 8; kc++) {
            unsigned a[4], breg[8][2];
            ldsm_x4(a[0], a[1], a[2], a[3], sptr(sQ + wm * ASTR + kc * 8 + a_off));
#pragma unroll
            for (int np = 0; np < 4; np++)
                ldsm_x4(breg[np * 2][0], breg[np * 2][1],
                        breg[np * 2 + 1][0], breg[np * 2 + 1][1],
                        sptr(sK + np * 16 * ASTR + kc * 8 + b_off));
#pragma unroll
            for (int nf = 0; nf < 8; nf++)
                mma_tf32(sacc[nf], a, breg[nf]);
        }

        const float scale = 0.125f;
        float rm0 = -1e30f, rm1 = -1e30f;
#pragma unroll
        for (int nf = 0; nf < 8; nf++) {
#pragma unroll
            for (int v = 0; v < 4; v++) sacc[nf][v] *= scale;
            rm0 = fmaxf(rm0, fmaxf(sacc[nf][0], sacc[nf][1]));
            rm1 = fmaxf(rm1, fmaxf(sacc[nf][2], sacc[nf][3]));
        }
#pragma unroll
        for (int off = 1; off < 4; off <<= 1) {
            rm0 = fmaxf(rm0, __shfl_xor_sync(0xffffffffu, rm0, off));
            rm1 = fmaxf(rm1, __shfl_xor_sync(0xffffffffu, rm1, off));
        }
        float mn0 = fmaxf(m0, rm0), mn1 = fmaxf(m1, rm1);
        float corr0 = __expf(m0 - mn0), corr1 = __expf(m1 - mn1);
        m0 = mn0; m1 = mn1;
        float rs0 = 0.f, rs1 = 0.f;
#pragma unroll
        for (int nf = 0; nf < 8; nf++) {
            float p0 = __expf(sacc[nf][0] - mn0);
            float p1 = __expf(sacc[nf][1] - mn0);
            float p2 = __expf(sacc[nf][2] - mn1);
            float p3 = __expf(sacc[nf][3] - mn1);
            sacc[nf][0] = p0; sacc[nf][1] = p1; sacc[nf][2] = p2; sacc[nf][3] = p3;
            rs0 += p0 + p1; rs1 += p2 + p3;
        }
#pragma unroll
        for (int off = 1; off < 4; off <<= 1) {
            rs0 += __shfl_xor_sync(0xffffffffu, rs0, off);
            rs1 += __shfl_xor_sync(0xffffffffu, rs1, off);
        }
        l0 = l0 * corr0 + rs0;
        l1 = l1 * corr1 + rs1;
#pragma unroll
        for (int nf = 0; nf < 8; nf++) {
            oacc[nf][0] *= corr0; oacc[nf][1] *= corr0;
            oacc[nf][2] *= corr1; oacc[nf][3] *= corr1;
        }

#pragma unroll
        for (int nf = 0; nf < 8; nf++) {
            uint2 lo = make_uint2(f2tf32(sacc[nf][0]), f2tf32(sacc[nf][1]));
            uint2 hi = make_uint2(f2tf32(sacc[nf][2]), f2tf32(sacc[nf][3]));
            *(uint2*)&sP[(wm + fr) * ASTR + nf * 8 + 2 * fc] = lo;
            *(uint2*)&sP[(wm + fr + 8) * ASTR + nf * 8 + 2 * fc] = hi;
        }
        __syncwarp();

#pragma unroll
        for (int kc = 0; kc < 8; kc++) {
            unsigned a[4], breg[8][2];
            ldsm_x4(a[0], a[1], a[2], a[3], sptr(sP + wm * ASTR + kc * 8 + a_off));
#pragma unroll
            for (int np = 0; np < 4; np++)
                ldsm_x4(breg[np * 2][0], breg[np * 2][1],
                        breg[np * 2 + 1][0], breg[np * 2 + 1][1],
                        sptr(sVt + np * 16 * ASTR + kc * 8 + b_off));
#pragma unroll
            for (int nf = 0; nf < 8; nf++)
                mma_tf32(oacc[nf], a, breg[nf]);
        }
    }

    const float inv0 = 1.0f / l0;
    const float inv1 = 1.0f / l1;
    const int b = bh / H_;
    const int h = bh % H_;
    const int r0 = q0 + wm + fr;
#pragma unroll
    for (int nf = 0; nf < 8; nf++) {
        int col = h * 64 + nf * 8 + 2 * fc;
        float2 lo = make_float2(oacc[nf][0] * inv0, oacc[nf][1] * inv0);
        float2 hi = make_float2(oacc[nf][2] * inv1, oacc[nf][3] * inv1);
        *(float2*)(out + (size_t)(b * N_ + r0) * C_ + col) = lo;
        *(float2*)(out + (size_t)(b * N_ + r0 + 8) * C_ + col) = hi;
    }
}

// ---------------------------------------------------------------------------
extern "C" void kernel_launch(void* const* d_in, const int* in_sizes, int n_in,
                              void* d_out, int out_size)
{
    const float* x_t    = (const float*)d_in[0];
    const float* qkv_w  = (const float*)d_in[1];
    const float* qkv_b  = (const float*)d_in[2];
    const float* proj_w = (const float*)d_in[3];
    const float* proj_b = (const float*)d_in[4];
    const int*   pos2d  = (const int*)d_in[5];
    float* out = (float*)d_out;

    float *p_qkv, *p_ao;
    cudaGetSymbolAddress((void**)&p_qkv, g_qkv);
    cudaGetSymbolAddress((void**)&p_ao, g_ao);

    cudaFuncSetAttribute(mma_gemm_bias,
                         cudaFuncAttributeMaxDynamicSharedMemorySize,
                         GEMM_SMEM_BYTES);
    cudaFuncSetAttribute(attn_mma_kernel,
                         cudaFuncAttributeMaxDynamicSharedMemorySize,
                         ATTN_SMEM_BYTES);

    // 1) QKV GEMM: [8192,768] x [2304,768]^T -> [8192,2304]
    {
        dim3 grid((3 * C_) / 256, (B_ * N_) / 128);
        mma_gemm_bias<<<grid, 256, GEMM_SMEM_BYTES>>>(x_t, qkv_w, qkv_b, p_qkv,
                                                      B_ * N_, 3 * C_, C_);
    }
    // 2) RoPE2D + split/transpose
    {
        int total = B_ * N_ * H_ * DH_;
        rope_split_kernel<<<(total + 255) / 256, 256>>>(pos2d);
    }
    // 3) Attention (tf32 MMA + LDSM)
    {
        dim3 grid(N_ / 64, B_ * H_);
        attn_mma_kernel<<<grid, 128, ATTN_SMEM_BYTES>>>(p_ao);
    }
    // 4) Output projection: [8192,768] x [768,768]^T -> [8192,768]
    {
        dim3 grid(C_ / 256, (B_ * N_) / 128);
        mma_gemm_bias<<<grid, 256, GEMM_SMEM_BYTES>>>(p_ao, proj_w, proj_b, out,
                                                      B_ * N_, C_, C_);
    }
}

// round 11
// speedup vs baseline: 1.7757x; 1.7757x over previous
#include <cuda_runtime.h>
#include <cuda_fp16.h>
#include <cstdint>
#include <stdint.h>
#include <math.h>

#define B_ 8
#define N_ 1024
#define C_ 768
#define H_ 12
#define DH_ 64
#define NIMG_ 784

// Scratch (static device arrays: allocation-free per harness rules)
__device__ float g_qkv[B_ * N_ * 3 * C_];       // [8192][2304]
__device__ float g_q[B_ * H_ * N_ * DH_];       // [bh][n][d]
__device__ float g_k[B_ * H_ * N_ * DH_];
__device__ float g_v[B_ * H_ * N_ * DH_];
__device__ float g_ao[B_ * N_ * C_];            // attention out, [b*N+n][C]

__device__ __forceinline__ unsigned packh2(float a, float b) {
    __half2 h = __floats2half2_rn(a, b);
    return *(unsigned*)&h;
}

__device__ __forceinline__ void mma_f16(float* d, const unsigned* a, const unsigned* b) {
    asm volatile(
        "mma.sync.aligned.m16n8k16.row.col.f32.f16.f16.f32 "
        "{%0,%1,%2,%3}, {%4,%5,%6,%7}, {%8,%9}, {%0,%1,%2,%3};"
        : "+f"(d[0]), "+f"(d[1]), "+f"(d[2]), "+f"(d[3])
        : "r"(a[0]), "r"(a[1]), "r"(a[2]), "r"(a[3]), "r"(b[0]), "r"(b[1]));
}

__device__ __forceinline__ unsigned sptr(const void* p) {
    return (unsigned)__cvta_generic_to_shared(p);
}

__device__ __forceinline__ void ldsm_x4(unsigned& r0, unsigned& r1,
                                        unsigned& r2, unsigned& r3, unsigned addr) {
    asm volatile("ldmatrix.sync.aligned.m8n8.x4.shared.b16 {%0,%1,%2,%3}, [%4];"
        : "=r"(r0), "=r"(r1), "=r"(r2), "=r"(r3) : "r"(addr));
}

// ---------------------------------------------------------------------------
// FP16 tensor-core GEMM (fp32 accumulate): out = A W^T + bias
// Block 128x128, BK=32 (two k16 steps), 256 threads = 8 warps (2m x 4n),
// warp tile 64x32. Double-buffered smem, 1 barrier/iter. LDSM fragment loads.
// Row stride 40 halves = 80 bytes (same conflict-free geometry as tf32 R7).
// ---------------------------------------------------------------------------
#define BKh 32
#define SSTRH 40
#define SA_H (128 * SSTRH)

__global__ void __launch_bounds__(256, 2) mma_gemm_bias(
    const float* __restrict__ A, const float* __restrict__ W,
    const float* __restrict__ bias, float* __restrict__ out,
    int M, int Nout, int K)
{
    __shared__ __align__(16) __half sA[2][SA_H];
    __shared__ __align__(16) __half sB[2][SA_H];

    const int t = threadIdx.x;
    const int lane = t & 31;
    const int warp = t >> 5;
    const int wm = (warp & 1) * 64;
    const int wn = (warp >> 1) * 32;
    const int m0 = blockIdx.y * 128;
    const int n0 = blockIdx.x * 128;

    // 128 rows x 32 cols f32 per tile: 1024 float4, 4 per thread
    int rg[4], cg[4];
#pragma unroll
    for (int i = 0; i < 4; i++) { rg[i] = (t + i * 256) >> 3; cg[i] = ((t + i * 256) & 7) * 4; }

    // LDSM per-lane offsets (halves)
    const int lg = lane >> 3, lr = lane & 7;
    const int a_off = ((lg & 1) * 8 + lr) * SSTRH + (lg >> 1) * 8;
    const int b_off = ((lg >> 1) * 8 + lr) * SSTRH + (lg & 1) * 8;

    float acc[4][4][4];
#pragma unroll
    for (int i = 0; i < 4; i++)
#pragma unroll
        for (int j = 0; j < 4; j++)
#pragma unroll
            for (int v = 0; v < 4; v++) acc[i][j][v] = 0.f;

    const int fr = lane >> 2;
    const int fc = lane & 3;

    float4 pa[4], pb[4];
#pragma unroll
    for (int i = 0; i < 4; i++) {
        pa[i] = *(const float4*)(A + (size_t)(m0 + rg[i]) * K + cg[i]);
        pb[i] = *(const float4*)(W + (size_t)(n0 + rg[i]) * K + cg[i]);
    }
#pragma unroll
    for (int i = 0; i < 4; i++) {
        *(uint2*)&sA[0][rg[i] * SSTRH + cg[i]] =
            make_uint2(packh2(pa[i].x, pa[i].y), packh2(pa[i].z, pa[i].w));
        *(uint2*)&sB[0][rg[i] * SSTRH + cg[i]] =
            make_uint2(packh2(pb[i].x, pb[i].y), packh2(pb[i].z, pb[i].w));
    }
    __syncthreads();

    const int nIter = K / BKh;
    for (int it = 0; it < nIter; it++) {
        const int buf = it & 1;
        const bool has_next = (it + 1) < nIter;

        if (has_next) {
            int kn = (it + 1) * BKh;
#pragma unroll
            for (int i = 0; i < 4; i++) {
                pa[i] = *(const float4*)(A + (size_t)(m0 + rg[i]) * K + kn + cg[i]);
                pb[i] = *(const float4*)(W + (size_t)(n0 + rg[i]) * K + kn + cg[i]);
            }
        }

        const __half* cA = sA[buf];
        const __half* cB = sB[buf];
#pragma unroll
        for (int ks = 0; ks < 2; ks++) {
            unsigned areg[4][4], breg[4][2];
#pragma unroll
            for (int mf = 0; mf < 4; mf++)
                ldsm_x4(areg[mf][0], areg[mf][1], areg[mf][2], areg[mf][3],
                        sptr(cA + (wm + mf * 16) * SSTRH + ks * 16 + a_off));
#pragma unroll
            for (int np = 0; np < 2; np++)
                ldsm_x4(breg[np * 2][0], breg[np * 2][1],
                        breg[np * 2 + 1][0], breg[np * 2 + 1][1],
                        sptr(cB + (wn + np * 16) * SSTRH + ks * 16 + b_off));
#pragma unroll
            for (int mf = 0; mf < 4; mf++)
#pragma unroll
                for (int nf = 0; nf < 4; nf++)
                    mma_f16(acc[mf][nf], areg[mf], breg[nf]);
        }

        if (has_next) {
            __half* nA = sA[buf ^ 1];
            __half* nB = sB[buf ^ 1];
#pragma unroll
            for (int i = 0; i < 4; i++) {
                *(uint2*)&nA[rg[i] * SSTRH + cg[i]] =
                    make_uint2(packh2(pa[i].x, pa[i].y), packh2(pa[i].z, pa[i].w));
                *(uint2*)&nB[rg[i] * SSTRH + cg[i]] =
                    make_uint2(packh2(pb[i].x, pb[i].y), packh2(pb[i].z, pb[i].w));
            }
            __syncthreads();
        }
    }

#pragma unroll
    for (int mf = 0; mf < 4; mf++) {
        int row = m0 + wm + mf * 16 + fr;
#pragma unroll
        for (int nf = 0; nf < 4; nf++) {
            int col = n0 + wn + nf * 8 + 2 * fc;
            float bx = bias[col], by = bias[col + 1];
            float2 lo = make_float2(acc[mf][nf][0] + bx, acc[mf][nf][1] + by);
            float2 hi = make_float2(acc[mf][nf][2] + bx, acc[mf][nf][3] + by);
            *(float2*)(out + (size_t)row * Nout + col) = lo;
            *(float2*)(out + (size_t)(row + 8) * Nout + col) = hi;
        }
    }
}

// ---------------------------------------------------------------------------
// RoPE2D + split qkv into q,k,v with [b*H+h][n][d] layout.
// ---------------------------------------------------------------------------
__global__ void rope_split_kernel(const int* __restrict__ pos2d)
{
    int idx = blockIdx.x * blockDim.x + threadIdx.x;
    const int total = B_ * N_ * H_ * DH_;
    if (idx >= total) return;

    int d = idx & 63;
    int h = (idx >> 6) % H_;
    int n = (idx / (H_ * DH_)) % N_;
    int b = idx / (N_ * H_ * DH_);

    const float* row = g_qkv + (size_t)(b * N_ + n) * (3 * C_);
    float qv = row[h * 64 + d];
    float kv = row[C_ + h * 64 + d];
    float vv = row[2 * C_ + h * 64 + d];

    if (n < NIMG_) {
        int half = d >> 5;
        int dl = d & 31;
        int f = dl & 15;
        int pos = pos2d[((size_t)b * NIMG_ + n) * 2 + half];
        float inv = exp2f(-0.41524101186f * (float)f);  // 100^(-f/16)
        float ang = (float)pos * inv;
        float s, c;
        sincosf(ang, &s, &c);
        int pd = (dl < 16) ? (d + 16) : (d - 16);
        float sign = (dl < 16) ? -1.0f : 1.0f;
        float qp = row[h * 64 + pd];
        float kp = row[C_ + h * 64 + pd];
        qv = qv * c + sign * qp * s;
        kv = kv * c + sign * kp * s;
    }

    size_t o = ((size_t)(b * H_ + h) * N_ + n) * DH_ + d;
    g_q[o] = qv; g_k[o] = kv; g_v[o] = vv;
}

// ---------------------------------------------------------------------------
// FP16 tensor-core flash attention (fp32 softmax/accumulators).
// Grid: (N/64, B*H). 128 threads = 4 warps, warp w owns q-rows [16w,16w+16).
// Row stride 72 halves = 144 bytes: each ldmatrix phase hits distinct banks.
// ---------------------------------------------------------------------------
#define ASTRH 72
#define ATTN_SMEM_BYTES (4 * 64 * ASTRH * 2)

__global__ void __launch_bounds__(128) attn_mma_kernel(float* __restrict__ out)
{
    extern __shared__ __align__(16) __half smh[];
    __half* sQ = smh;
    __half* sK = smh + 64 * ASTRH;
    __half* sVt = smh + 2 * 64 * ASTRH;
    __half* sP = smh + 3 * 64 * ASTRH;

    const int t = threadIdx.x;
    const int lane = t & 31;
    const int w = t >> 5;
    const int fr = lane >> 2;
    const int fc = lane & 3;
    const int wm = w * 16;
    const int bh = blockIdx.y;
    const int q0 = blockIdx.x * 64;

    const int lg = lane >> 3, lr = lane & 7;
    const int a_off = ((lg & 1) * 8 + lr) * ASTRH + (lg >> 1) * 8;
    const int b_off = ((lg >> 1) * 8 + lr) * ASTRH + (lg & 1) * 8;

    const float* Qg = g_q + ((size_t)bh * N_ + q0) * DH_;
    const float* Kg = g_k + (size_t)bh * N_ * DH_;
    const float* Vg = g_v + (size_t)bh * N_ * DH_;

    // Q tile 64x64: 1024 float4, 8 per thread
#pragma unroll
    for (int i = 0; i < 8; i++) {
        int idx4 = t + i * 128;
        int r = idx4 >> 4;
        int c4 = (idx4 & 15) * 4;
        float4 v4 = *(const float4*)(Qg + (size_t)r * 64 + c4);
        *(uint2*)&sQ[r * ASTRH + c4] =
            make_uint2(packh2(v4.x, v4.y), packh2(v4.z, v4.w));
    }

    float m0 = -1e30f, m1 = -1e30f, l0 = 0.f, l1 = 0.f;
    float oacc[8][4];
#pragma unroll
    for (int nf = 0; nf < 8; nf++)
#pragma unroll
        for (int v = 0; v < 4; v++) oacc[nf][v] = 0.f;

    const int vd = 32 * (w & 1) + lane;
    const int vkb = (w >> 1) * 4;

    for (int kb = 0; kb < N_; kb += 64) {
        if (kb) __syncthreads();
#pragma unroll
        for (int i = 0; i < 8; i++) {
            int idx4 = t + i * 128;
            int r = idx4 >> 4;
            int c4 = (idx4 & 15) * 4;
            float4 k4 = *(const float4*)(Kg + (size_t)(kb + r) * 64 + c4);
            *(uint2*)&sK[r * ASTRH + c4] =
                make_uint2(packh2(k4.x, k4.y), packh2(k4.z, k4.w));
        }
#pragma unroll
        for (int i = 0; i < 8; i++) {
            int key0 = vkb + i * 8;
            float v0 = Vg[(size_t)(kb + key0 + 0) * 64 + vd];
            float v1 = Vg[(size_t)(kb + key0 + 1) * 64 + vd];
            float v2 = Vg[(size_t)(kb + key0 + 2) * 64 + vd];
            float v3 = Vg[(size_t)(kb + key0 + 3) * 64 + vd];
            *(uint2*)&sVt[vd * ASTRH + key0] =
                make_uint2(packh2(v0, v1), packh2(v2, v3));
        }
        __syncthreads();

        // S = Q K^T : 4 k16 steps
        float sacc[8][4];
#pragma unroll
        for (int nf = 0; nf < 8; nf++)
#pragma unroll
            for (int v = 0; v < 4; v++) sacc[nf][v] = 0.f;
#pragma unroll
        for (int kc = 0; kc < 4; kc++) {
            unsigned a[4], breg[8][2];
            ldsm_x4(a[0], a[1], a[2], a[3], sptr(sQ + wm * ASTRH + kc * 16 + a_off));
#pragma unroll
            for (int np = 0; np < 4; np++)
                ldsm_x4(breg[np * 2][0], breg[np * 2][1],
                        breg[np * 2 + 1][0], breg[np * 2 + 1][1],
                        sptr(sK + np * 16 * ASTRH + kc * 16 + b_off));
#pragma unroll
            for (int nf = 0; nf < 8; nf++)
                mma_f16(sacc[nf], a, breg[nf]);
        }

        const float scale = 0.125f;
        float rm0 = -1e30f, rm1 = -1e30f;
#pragma unroll
        for (int nf = 0; nf < 8; nf++) {
#pragma unroll
            for (int v = 0; v < 4; v++) sacc[nf][v] *= scale;
            rm0 = fmaxf(rm0, fmaxf(sacc[nf][0], sacc[nf][1]));
            rm1 = fmaxf(rm1, fmaxf(sacc[nf][2], sacc[nf][3]));
        }
#pragma unroll
        for (int off = 1; off < 4; off <<= 1) {
            rm0 = fmaxf(rm0, __shfl_xor_sync(0xffffffffu, rm0, off));
            rm1 = fmaxf(rm1, __shfl_xor_sync(0xffffffffu, rm1, off));
        }
        float mn0 = fmaxf(m0, rm0), mn1 = fmaxf(m1, rm1);
        float corr0 = __expf(m0 - mn0), corr1 = __expf(m1 - mn1);
        m0 = mn0; m1 = mn1;
        float rs0 = 0.f, rs1 = 0.f;
#pragma unroll
        for (int nf = 0; nf < 8; nf++) {
            float p0 = __expf(sacc[nf][0] - mn0);
            float p1 = __expf(sacc[nf][1] - mn0);
            float p2 = __expf(sacc[nf][2] - mn1);
            float p3 = __expf(sacc[nf][3] - mn1);
            sacc[nf][0] = p0; sacc[nf][1] = p1; sacc[nf][2] = p2; sacc[nf][3] = p3;
            rs0 += p0 + p1; rs1 += p2 + p3;
        }
#pragma unroll
        for (int off = 1; off < 4; off <<= 1) {
            rs0 += __shfl_xor_sync(0xffffffffu, rs0, off);
            rs1 += __shfl_xor_sync(0xffffffffu, rs1, off);
        }
        l0 = l0 * corr0 + rs0;
        l1 = l1 * corr1 + rs1;
#pragma unroll
        for (int nf = 0; nf < 8; nf++) {
            oacc[nf][0] *= corr0; oacc[nf][1] *= corr0;
            oacc[nf][2] *= corr1; oacc[nf][3] *= corr1;
        }

        // P -> sP as fp16 (warp-private rows)
#pragma unroll
        for (int nf = 0; nf < 8; nf++) {
            *(unsigned*)&sP[(wm + fr) * ASTRH + nf * 8 + 2 * fc] =
                packh2(sacc[nf][0], sacc[nf][1]);
            *(unsigned*)&sP[(wm + fr + 8) * ASTRH + nf * 8 + 2 * fc] =
                packh2(sacc[nf][2], sacc[nf][3]);
        }
        __syncwarp();

        // O += P V : 4 k16 steps
#pragma unroll
        for (int kc = 0; kc < 4; kc++) {
            unsigned a[4], breg[8][2];
            ldsm_x4(a[0], a[1], a[2], a[3], sptr(sP + wm * ASTRH + kc * 16 + a_off));
#pragma unroll
            for (int np = 0; np < 4; np++)
                ldsm_x4(breg[np * 2][0], breg[np * 2][1],
                        breg[np * 2 + 1][0], breg[np * 2 + 1][1],
                        sptr(sVt + np * 16 * ASTRH + kc * 16 + b_off));
#pragma unroll
            for (int nf = 0; nf < 8; nf++)
                mma_f16(oacc[nf], a, breg[nf]);
        }
    }

    const float inv0 = 1.0f / l0;
    const float inv1 = 1.0f / l1;
    const int b = bh / H_;
    const int h = bh % H_;
    const int r0 = q0 + wm + fr;
#pragma unroll
    for (int nf = 0; nf < 8; nf++) {
        int col = h * 64 + nf * 8 + 2 * fc;
        float2 lo = make_float2(oacc[nf][0] * inv0, oacc[nf][1] * inv0);
        float2 hi = make_float2(oacc[nf][2] * inv1, oacc[nf][3] * inv1);
        *(float2*)(out + (size_t)(b * N_ + r0) * C_ + col) = lo;
        *(float2*)(out + (size_t)(b * N_ + r0 + 8) * C_ + col) = hi;
    }
}

// ---------------------------------------------------------------------------
extern "C" void kernel_launch(void* const* d_in, const int* in_sizes, int n_in,
                              void* d_out, int out_size)
{
    const float* x_t    = (const float*)d_in[0];
    const float* qkv_w  = (const float*)d_in[1];
    const float* qkv_b  = (const float*)d_in[2];
    const float* proj_w = (const float*)d_in[3];
    const float* proj_b = (const float*)d_in[4];
    const int*   pos2d  = (const int*)d_in[5];
    float* out = (float*)d_out;

    float *p_qkv, *p_ao;
    cudaGetSymbolAddress((void**)&p_qkv, g_qkv);
    cudaGetSymbolAddress((void**)&p_ao, g_ao);

    cudaFuncSetAttribute(attn_mma_kernel,
                         cudaFuncAttributeMaxDynamicSharedMemorySize,
                         ATTN_SMEM_BYTES);

    // 1) QKV GEMM: [8192,768] x [2304,768]^T -> [8192,2304]
    {
        dim3 grid((3 * C_) / 128, (B_ * N_) / 128);
        mma_gemm_bias<<<grid, 256>>>(x_t, qkv_w, qkv_b, p_qkv,
                                     B_ * N_, 3 * C_, C_);
    }
    // 2) RoPE2D + split/transpose
    {
        int total = B_ * N_ * H_ * DH_;
        rope_split_kernel<<<(total + 255) / 256, 256>>>(pos2d);
    }
    // 3) Attention (fp16 MMA + LDSM)
    {
        dim3 grid(N_ / 64, B_ * H_);
        attn_mma_kernel<<<grid, 128, ATTN_SMEM_BYTES>>>(p_ao);
    }
    // 4) Output projection: [8192,768] x [768,768]^T -> [8192,768]
    {
        dim3 grid(C_ / 128, (B_ * N_) / 128);
        mma_gemm_bias<<<grid, 256>>>(p_ao, proj_w, proj_b, out,
                                     B_ * N_, C_, C_);
    }
}